// round 15
// baseline (speedup 1.0000x reference)
#include <cuda_runtime.h>
#include <cuda_fp16.h>
#include <cstdint>

// GraphSAGE: N=50000, E=800000, 128 -> 128 -> 128 -> 32
// FUSED agg+GEMM layers (fp16 pipeline, retry of R9 with fixed occupancy):
//  - F1/F2/F3: [gather-aggregate 128 rows into smem fp16] -> [tensor GEMM]
//    in one kernel; agg output never touches global. 52KB smem, ~2 CTA/SM.
//  - norm, L0 GEMM pair (parallel streams), final agg32 stay separate.
//  - PDL on the serial tail; fork-join CSR + wsplit off-path.
//  - fp16 activations; W 2-term fp16 split; L0-self + L3 fp32 high-weight terms.

#define NN 50000
#define FDIM 128
#define OUTF 32
#define CAP 96

__device__ __half g_wh[73728];
__device__ __half g_wl[73728];
__device__ float  g_t0[NN * FDIM];
__device__ __half g_qa[NN * FDIM];
__device__ __half g_qb[NN * FDIM];
__device__ int    g_cnt[NN];
__device__ int    g_col[NN * CAP];
__device__ int    g_is64;

// ---------------------------------------------------------------------------
__device__ __forceinline__ void split_fp16(float v, __half& hi, __half& lo) {
    hi = __float2half_rn(v);
    lo = __float2half_rn(v - __half2float(hi));
}

__device__ __forceinline__ void cpa16(uint32_t dst, const void* src, int szz) {
    asm volatile("cp.async.ca.shared.global [%0], [%1], 16, %2;"
                 :: "r"(dst), "l"(src), "r"(szz));
}
#define CP_COMMIT asm volatile("cp.async.commit_group;" ::: "memory")
#define CP_WAIT1  asm volatile("cp.async.wait_group 1;" ::: "memory")
#define CP_WAIT0  asm volatile("cp.async.wait_group 0;" ::: "memory")

__device__ __forceinline__ void ldsm4(uint32_t r[4], uint32_t addr) {
    asm volatile("ldmatrix.sync.aligned.m8n8.x4.shared.b16 {%0,%1,%2,%3}, [%4];"
                 : "=r"(r[0]), "=r"(r[1]), "=r"(r[2]), "=r"(r[3]) : "r"(addr));
}
__device__ __forceinline__ void ldsm4t(uint32_t r[4], uint32_t addr) {
    asm volatile("ldmatrix.sync.aligned.m8n8.x4.trans.shared.b16 {%0,%1,%2,%3}, [%4];"
                 : "=r"(r[0]), "=r"(r[1]), "=r"(r[2]), "=r"(r[3]) : "r"(addr));
}
__device__ __forceinline__ void mma16816(float d[4], const uint32_t a[4],
                                         const uint32_t* b) {
    asm volatile(
        "mma.sync.aligned.m16n8k16.row.col.f32.f16.f16.f32 "
        "{%0,%1,%2,%3}, {%4,%5,%6,%7}, {%8,%9}, {%0,%1,%2,%3};"
        : "+f"(d[0]), "+f"(d[1]), "+f"(d[2]), "+f"(d[3])
        : "r"(a[0]), "r"(a[1]), "r"(a[2]), "r"(a[3]), "r"(b[0]), "r"(b[1]));
}

// ---------------------------------------------------------------------------
__device__ __forceinline__ int eidx(const void* p, int i, int is64) {
    return is64 ? (int)((const long long*)p)[i] : ((const int*)p)[i];
}

__global__ void k_zero_detect(const int* w, int n, int e) {
    for (int i = blockIdx.x * blockDim.x + threadIdx.x; i < e;
         i += gridDim.x * blockDim.x) {
        if (i < n) g_cnt[i] = 0;
        if ((i & 1) && w[i] != 0) g_is64 = 0;
    }
}

__global__ void k_scatter(const void* src, const void* dst, int e) {
    int is64 = g_is64;
    for (int i = blockIdx.x * blockDim.x + threadIdx.x; i < e;
         i += gridDim.x * blockDim.x) {
        int d = eidx(dst, i, is64);
        int p = atomicAdd(&g_cnt[d], 1);
        if (p < CAP) g_col[d * CAP + p] = eidx(src, i, is64);
    }
}

// ---------------------------------------------------------------------------
// Weight pre-split (fp16 hi/lo):
// [0)=Wself0 [16384)=Wneigh0 [32768)=Wneigh1 [49152)=Wneigh2
// [65536, 73728) = concat(Wself3 | Wneigh3) as [128 x 64]
// ---------------------------------------------------------------------------
__global__ void k_wsplit(const float* __restrict__ ws0, const float* __restrict__ wn0,
                         const float* __restrict__ wn1, const float* __restrict__ wn2,
                         const float* __restrict__ ws3, const float* __restrict__ wn3) {
    int i = blockIdx.x * blockDim.x + threadIdx.x;
    if (i >= 73728) return;
    float v;
    if (i < 16384) v = ws0[i];
    else if (i < 32768) v = wn0[i - 16384];
    else if (i < 49152) v = wn1[i - 32768];
    else if (i < 65536) v = wn2[i - 49152];
    else {
        int j = i - 65536, r = j >> 6, c = j & 63;
        v = (c < 32) ? ws3[r * 32 + c] : wn3[r * 32 + c - 32];
    }
    __half hi, lo;
    split_fp16(v, hi, lo);
    g_wh[i] = hi;
    g_wl[i] = lo;
}

// ---------------------------------------------------------------------------
// L2 normalize: half-warp per node
// ---------------------------------------------------------------------------
__global__ void k_norm(const float* __restrict__ x, __half* __restrict__ q, int n) {
    int hw = (blockIdx.x * blockDim.x + threadIdx.x) >> 4;
    int l = threadIdx.x & 15;
    if (hw >= n) return;
    size_t base = (size_t)hw * FDIM + l * 8;
    float4 a = *(const float4*)(x + base);
    float4 b = *(const float4*)(x + base + 4);
    float ss = a.x * a.x + a.y * a.y + a.z * a.z + a.w * a.w +
               b.x * b.x + b.y * b.y + b.z * b.z + b.w * b.w;
    #pragma unroll
    for (int o = 8; o; o >>= 1) ss += __shfl_xor_sync(0xFFFFFFFFu, ss, o, 16);
    float s = 1.0f / fmaxf(sqrtf(ss), 1e-12f);
    uint4 pk;
    ((__half2*)&pk)[0] = __float22half2_rn(make_float2(a.x * s, a.y * s));
    ((__half2*)&pk)[1] = __float22half2_rn(make_float2(a.z * s, a.w * s));
    ((__half2*)&pk)[2] = __float22half2_rn(make_float2(b.x * s, b.y * s));
    ((__half2*)&pk)[3] = __float22half2_rn(make_float2(b.z * s, b.w * s));
    *(uint4*)(q + base) = pk;
}

// ---------------------------------------------------------------------------
// shared helpers for GEMM staging / gather
// ---------------------------------------------------------------------------
template <int M>
__device__ __forceinline__ void stage_w(uint32_t dWh, uint32_t dWl,
                                        const __half* __restrict__ Wgh,
                                        const __half* __restrict__ Wgl,
                                        int k0, int tid) {
    constexpr int CW = M / 8;
    #pragma unroll
    for (int i = tid; i < 2 * 16 * CW; i += 256) {
        int half_ = i / (16 * CW), rem = i % (16 * CW);
        int r = rem / CW, seg = rem % CW;
        size_t so = (size_t)(k0 + r) * M + seg * 8;
        uint32_t dof = (uint32_t)(r * (M + 8) + seg * 8) * 2;
        if (half_ == 0) cpa16(dWh + dof, Wgh + so, 16);
        else            cpa16(dWl + dof, Wgl + so, 16);
    }
}

__device__ __forceinline__ float4 h4_to_f4(uint2 raw) {
    __half2 p0 = *(__half2*)&raw.x;
    __half2 p1 = *(__half2*)&raw.y;
    float2 f0 = __half22float2(p0), f1 = __half22float2(p1);
    return make_float4(f0.x, f0.y, f1.x, f1.y);
}
__device__ __forceinline__ void acc4(float4& a, float4 t) {
    a.x += t.x; a.y += t.y; a.z += t.z; a.w += t.w;
}

__device__ __forceinline__ float4 gather_sum(const __half* __restrict__ q,
                                             int v, int lane, int dt) {
    int L = dt < CAP ? dt : CAP;
    const int* cp = g_col + v * CAP;
    float4 acc = make_float4(0.f, 0.f, 0.f, 0.f);
    int j = 0;
    for (; j + 8 <= L; j += 8) {
        int4 u0 = *(const int4*)(cp + j);
        int4 u1 = *(const int4*)(cp + j + 4);
        uint2 a0 = *(const uint2*)(q + (size_t)u0.x * FDIM + lane * 4);
        uint2 a1 = *(const uint2*)(q + (size_t)u0.y * FDIM + lane * 4);
        uint2 a2 = *(const uint2*)(q + (size_t)u0.z * FDIM + lane * 4);
        uint2 a3 = *(const uint2*)(q + (size_t)u0.w * FDIM + lane * 4);
        uint2 a4 = *(const uint2*)(q + (size_t)u1.x * FDIM + lane * 4);
        uint2 a5 = *(const uint2*)(q + (size_t)u1.y * FDIM + lane * 4);
        uint2 a6 = *(const uint2*)(q + (size_t)u1.z * FDIM + lane * 4);
        uint2 a7 = *(const uint2*)(q + (size_t)u1.w * FDIM + lane * 4);
        acc4(acc, h4_to_f4(a0)); acc4(acc, h4_to_f4(a1));
        acc4(acc, h4_to_f4(a2)); acc4(acc, h4_to_f4(a3));
        acc4(acc, h4_to_f4(a4)); acc4(acc, h4_to_f4(a5));
        acc4(acc, h4_to_f4(a6)); acc4(acc, h4_to_f4(a7));
    }
    for (; j + 4 <= L; j += 4) {
        int4 u = *(const int4*)(cp + j);
        uint2 a0 = *(const uint2*)(q + (size_t)u.x * FDIM + lane * 4);
        uint2 a1 = *(const uint2*)(q + (size_t)u.y * FDIM + lane * 4);
        uint2 a2 = *(const uint2*)(q + (size_t)u.z * FDIM + lane * 4);
        uint2 a3 = *(const uint2*)(q + (size_t)u.w * FDIM + lane * 4);
        acc4(acc, h4_to_f4(a0)); acc4(acc, h4_to_f4(a1));
        acc4(acc, h4_to_f4(a2)); acc4(acc, h4_to_f4(a3));
    }
    for (; j < L; j++) {
        int u = cp[j];
        acc4(acc, h4_to_f4(*(const uint2*)(q + (size_t)u * FDIM + lane * 4)));
    }
    return acc;
}

// ---------------------------------------------------------------------------
// Plain fp16 GEMM (for layer 0). OUTMODE: 0 = fp32 C; 1 = fp16 Q.
// ---------------------------------------------------------------------------
__device__ __forceinline__ void stage_a(uint32_t dA, const __half* __restrict__ Ag,
                                        int row0, int k0, int n, int tid) {
    int r = tid >> 1, seg = tid & 1;
    int row = row0 + r;
    int ok = (row < n) ? 16 : 0;
    size_t so = (size_t)(ok ? row : 0) * 128 + k0 + seg * 8;
    uint32_t dof = (uint32_t)(r * 24 + seg * 8) * 2;
    cpa16(dA + dof, Ag + so, ok);
}

template <int M, int OUTMODE>
__global__ void __launch_bounds__(256) k_gemm_h(
    const __half* __restrict__ Ag,
    const __half* __restrict__ Wgh, const __half* __restrict__ Wgl,
    float* __restrict__ C, __half* __restrict__ Q, int n) {
    constexpr int LDA = 24;
    constexpr int LDB = M + 8;
    constexpr int NT  = M / 16;
    __shared__ __half A[2][128 * LDA];
    __shared__ __half Wh[2][16 * LDB], Wl[2][16 * LDB];

    int tid = threadIdx.x;
    int lane = tid & 31, wid = tid >> 5;
    int row0 = blockIdx.x * 128;

    float acc[NT][2][4];
    #pragma unroll
    for (int t = 0; t < NT; t++)
        #pragma unroll
        for (int s = 0; s < 2; s++)
            #pragma unroll
            for (int c = 0; c < 4; c++) acc[t][s][c] = 0.f;

    uint32_t sA[2]  = {(uint32_t)__cvta_generic_to_shared(A[0]),
                       (uint32_t)__cvta_generic_to_shared(A[1])};
    uint32_t sWh[2] = {(uint32_t)__cvta_generic_to_shared(Wh[0]),
                       (uint32_t)__cvta_generic_to_shared(Wh[1])};
    uint32_t sWl[2] = {(uint32_t)__cvta_generic_to_shared(Wl[0]),
                       (uint32_t)__cvta_generic_to_shared(Wl[1])};

    stage_w<M>(sWh[0], sWl[0], Wgh, Wgl, 0, tid);
    CP_COMMIT;

    cudaGridDependencySynchronize();

    stage_a(sA[0], Ag, row0, 0, n, tid);
    CP_COMMIT;

    #pragma unroll
    for (int c = 0; c < 8; c++) {
        int b = c & 1;
        if (c < 7) {
            int nb = (c + 1) & 1;
            stage_w<M>(sWh[nb], sWl[nb], Wgh, Wgl, (c + 1) * 16, tid);
            stage_a(sA[nb], Ag, row0, (c + 1) * 16, n, tid);
            CP_COMMIT;
            CP_WAIT1;
        } else {
            CP_WAIT0;
        }
        __syncthreads();

        uint32_t aoff = ((wid * 16 + (lane & 15)) * LDA + (lane >> 4) * 8) * 2;
        uint32_t a[4];
        ldsm4(a, sA[b] + aoff);
        #pragma unroll
        for (int nt = 0; nt < NT; nt++) {
            uint32_t boff = ((lane & 15) * LDB + nt * 16 + (lane >> 4) * 8) * 2;
            uint32_t bh[4], bl[4];
            ldsm4t(bh, sWh[b] + boff);
            ldsm4t(bl, sWl[b] + boff);
            mma16816(acc[nt][0], a, bh + 0);
            mma16816(acc[nt][1], a, bh + 2);
            mma16816(acc[nt][0], a, bl + 0);
            mma16816(acc[nt][1], a, bl + 2);
        }
        __syncthreads();
    }

    int g = lane >> 2, tg = lane & 3;
    int r0 = row0 + wid * 16 + g;
    #pragma unroll
    for (int nt = 0; nt < NT; nt++) {
        #pragma unroll
        for (int s = 0; s < 2; s++) {
            int col = nt * 16 + s * 8 + tg * 2;
            float2 v01 = make_float2(acc[nt][s][0], acc[nt][s][1]);
            float2 v23 = make_float2(acc[nt][s][2], acc[nt][s][3]);
            #pragma unroll
            for (int rr = 0; rr < 2; rr++) {
                int r = r0 + rr * 8;
                float2 v = rr ? v23 : v01;
                if (r >= n) continue;
                if (OUTMODE == 0)
                    *(float2*)(C + (size_t)r * M + col) = v;
                else
                    *(__half2*)(Q + (size_t)r * M + col) = __float22half2_rn(v);
            }
        }
    }
}

// ---------------------------------------------------------------------------
// FUSED agg+GEMM: produce 128 rows (MODE 1=mean-agg, 2=gcn-agg) into smem
// fp16, then GEMM vs [128,M] split weights.
// OUTMODE: 1 = fp16 Q[n,M]; 2 = (M=64) fp32 C[n,64] + fp16 mirror Q[n,32].
// Dynamic smem: As[128*136] | Wh[2][16*LDB] | Wl[2][16*LDB].
// ---------------------------------------------------------------------------
template <int MODE, int M, int OUTMODE>
__global__ void __launch_bounds__(256) k_fused(
    const float* __restrict__ tself,   // fp32 self term (MODE 1)
    const __half* __restrict__ qin,    // fp16 activation in (gather + self M2)
    const float* __restrict__ bias,
    const __half* __restrict__ Wgh, const __half* __restrict__ Wgl,
    float* __restrict__ C, __half* __restrict__ Q, int n) {
    constexpr int LDA = 136;                 // 272B rows, ldsm conflict-free
    constexpr int LDB = M + 8;
    constexpr int NT  = M / 16;
    constexpr int AH  = 128 * LDA;           // halves

    extern __shared__ __half sm[];
    __half* As = sm;
    uint32_t sA  = (uint32_t)__cvta_generic_to_shared(sm);
    uint32_t sWh[2] = {sA + AH * 2, sA + (AH + 16 * LDB) * 2};
    uint32_t sWl[2] = {sA + (AH + 32 * LDB) * 2, sA + (AH + 48 * LDB) * 2};

    int tid = threadIdx.x;
    int lane = tid & 31, wid = tid >> 5;
    int row0 = blockIdx.x * 128;

    // prologue (weights ready): stage W chunk 0
    stage_w<M>(sWh[0], sWl[0], Wgh, Wgl, 0, tid);
    CP_COMMIT;

    cudaGridDependencySynchronize();   // predecessor produced qin/tself

    // ---- phase A: aggregate 16 nodes per warp into smem ----
    #pragma unroll 1
    for (int i = 0; i < 16; i++) {
        int lr = wid * 16 + i;
        int v = row0 + lr;
        float4 o = make_float4(0.f, 0.f, 0.f, 0.f);
        if (v < n) {
            int dt = g_cnt[v];
            float4 acc = gather_sum(qin, v, lane, dt);
            float4 bb = *(const float4*)(bias + lane * 4);
            if (MODE == 1) {
                float inv = 1.0f / fmaxf((float)dt, 1.0f);
                float4 sf = *(const float4*)(tself + (size_t)v * FDIM + lane * 4);
                o.x = fmaxf(sf.x + acc.x * inv + bb.x, 0.f);
                o.y = fmaxf(sf.y + acc.y * inv + bb.y, 0.f);
                o.z = fmaxf(sf.z + acc.z * inv + bb.z, 0.f);
                o.w = fmaxf(sf.w + acc.w * inv + bb.w, 0.f);
            } else {
                float4 sf =
                    h4_to_f4(*(const uint2*)(qin + (size_t)v * FDIM + lane * 4));
                acc4(acc, sf);
                float inv = 1.0f / ((float)dt + 1.0f);
                o.x = fmaxf(acc.x * inv + bb.x, 0.f);
                o.y = fmaxf(acc.y * inv + bb.y, 0.f);
                o.z = fmaxf(acc.z * inv + bb.z, 0.f);
                o.w = fmaxf(acc.w * inv + bb.w, 0.f);
            }
        }
        int off = lr * LDA + lane * 4;
        *(__half2*)(As + off)     = __float22half2_rn(make_float2(o.x, o.y));
        *(__half2*)(As + off + 2) = __float22half2_rn(make_float2(o.z, o.w));
    }
    __syncthreads();

    // ---- phase B: GEMM, K=128 in 8 chunks of 16 (W double-buffered) ----
    float acc[NT][2][4];
    #pragma unroll
    for (int t = 0; t < NT; t++)
        #pragma unroll
        for (int s = 0; s < 2; s++)
            #pragma unroll
            for (int c = 0; c < 4; c++) acc[t][s][c] = 0.f;

    #pragma unroll
    for (int c = 0; c < 8; c++) {
        int b = c & 1;
        if (c < 7) {
            stage_w<M>(sWh[(c + 1) & 1], sWl[(c + 1) & 1], Wgh, Wgl,
                       (c + 1) * 16, tid);
            CP_COMMIT;
            CP_WAIT1;
        } else {
            CP_WAIT0;
        }
        __syncthreads();

        uint32_t aoff =
            ((wid * 16 + (lane & 15)) * LDA + c * 16 + (lane >> 4) * 8) * 2;
        uint32_t a[4];
        ldsm4(a, sA + aoff);
        #pragma unroll
        for (int nt = 0; nt < NT; nt++) {
            uint32_t boff = ((lane & 15) * LDB + nt * 16 + (lane >> 4) * 8) * 2;
            uint32_t bh[4], bl[4];
            ldsm4t(bh, sWh[b] + boff);
            ldsm4t(bl, sWl[b] + boff);
            mma16816(acc[nt][0], a, bh + 0);
            mma16816(acc[nt][1], a, bh + 2);
            mma16816(acc[nt][0], a, bl + 0);
            mma16816(acc[nt][1], a, bl + 2);
        }
        __syncthreads();
    }

    int g = lane >> 2, tg = lane & 3;
    int r0 = row0 + wid * 16 + g;
    #pragma unroll
    for (int nt = 0; nt < NT; nt++) {
        #pragma unroll
        for (int s = 0; s < 2; s++) {
            int col = nt * 16 + s * 8 + tg * 2;
            float2 v01 = make_float2(acc[nt][s][0], acc[nt][s][1]);
            float2 v23 = make_float2(acc[nt][s][2], acc[nt][s][3]);
            #pragma unroll
            for (int rr = 0; rr < 2; rr++) {
                int r = r0 + rr * 8;
                float2 v = rr ? v23 : v01;
                if (r >= n) continue;
                if (OUTMODE == 1) {
                    *(__half2*)(Q + (size_t)r * M + col) = __float22half2_rn(v);
                } else {  // OUTMODE 2 (M=64): fp32 + fp16 mirror of cols>=32
                    *(float2*)(C + (size_t)r * 64 + col) = v;
                    if (col >= 32)
                        *(__half2*)(Q + (size_t)r * 32 + col - 32) =
                            __float22half2_rn(v);
                }
            }
        }
    }
}

// ---------------------------------------------------------------------------
// Final aggregation (layer 3): self fp32 t[n,64] cols 0-31; neigh fp16 qn[n,32]
// ---------------------------------------------------------------------------
__global__ void k_agg_mean32(const float* __restrict__ t,
                             const __half* __restrict__ qn,
                             const float* __restrict__ b,
                             float* __restrict__ out, int n) {
    int v = (blockIdx.x * blockDim.x + threadIdx.x) >> 5;
    int lane = threadIdx.x & 31;
    if (v >= n) { cudaGridDependencySynchronize(); return; }
    int dt = g_cnt[v];
    cudaGridDependencySynchronize();
    int L = dt < CAP ? dt : CAP;
    const int* cp = g_col + v * CAP;
    float acc = 0.f;
    int j = 0;
    for (; j + 8 <= L; j += 8) {
        int4 u0 = *(const int4*)(cp + j);
        int4 u1 = *(const int4*)(cp + j + 4);
        float a0 = __half2float(qn[(size_t)u0.x * 32 + lane]);
        float a1 = __half2float(qn[(size_t)u0.y * 32 + lane]);
        float a2 = __half2float(qn[(size_t)u0.z * 32 + lane]);
        float a3 = __half2float(qn[(size_t)u0.w * 32 + lane]);
        float a4 = __half2float(qn[(size_t)u1.x * 32 + lane]);
        float a5 = __half2float(qn[(size_t)u1.y * 32 + lane]);
        float a6 = __half2float(qn[(size_t)u1.z * 32 + lane]);
        float a7 = __half2float(qn[(size_t)u1.w * 32 + lane]);
        acc += a0 + a1 + a2 + a3 + a4 + a5 + a6 + a7;
    }
    for (; j < L; j++)
        acc += __half2float(qn[(size_t)cp[j] * 32 + lane]);
    float inv = 1.0f / fmaxf((float)dt, 1.0f);
    out[(size_t)v * OUTF + lane] = t[(size_t)v * 64 + lane] + acc * inv + b[lane];
}

// ---------------------------------------------------------------------------
extern "C" void kernel_launch(void* const* d_in, const int* in_sizes, int n_in,
                              void* d_out, int out_size) {
    const float* x       = (const float*)d_in[0];
    const void*  src     = d_in[1];
    const void*  dst     = d_in[2];
    const float* Wself0  = (const float*)d_in[3];
    const float* Wneigh0 = (const float*)d_in[4];
    const float* b0      = (const float*)d_in[5];
    const float* Wneigh1 = (const float*)d_in[6];
    const float* b1      = (const float*)d_in[7];
    const float* Wneigh2 = (const float*)d_in[8];
    const float* b2      = (const float*)d_in[9];
    const float* Wself3  = (const float*)d_in[10];
    const float* Wneigh3 = (const float*)d_in[11];
    const float* b3      = (const float*)d_in[12];
    float* out = (float*)d_out;

    int n = in_sizes[0] / FDIM;
    int e = in_sizes[1];

    __half *wh, *wl, *qa, *qb;
    float* t0;
    int* is64p;
    cudaGetSymbolAddress((void**)&wh, g_wh);
    cudaGetSymbolAddress((void**)&wl, g_wl);
    cudaGetSymbolAddress((void**)&qa, g_qa);
    cudaGetSymbolAddress((void**)&qb, g_qb);
    cudaGetSymbolAddress((void**)&t0, g_t0);
    cudaGetSymbolAddress((void**)&is64p, g_is64);

    constexpr int SM_F128 = (128 * 136 + 4 * 16 * 136) * 2;  // 52224
    constexpr int SM_F64  = (128 * 136 + 4 * 16 * 72) * 2;   // 44032

    static cudaStream_t s1 = nullptr, s2 = nullptr;
    static cudaEvent_t eFork = nullptr, eCSR = nullptr, eW = nullptr,
                       eN = nullptr, eG1 = nullptr;
    if (!s1) {
        cudaStreamCreateWithFlags(&s1, cudaStreamNonBlocking);
        cudaStreamCreateWithFlags(&s2, cudaStreamNonBlocking);
        cudaEventCreateWithFlags(&eFork, cudaEventDisableTiming);
        cudaEventCreateWithFlags(&eCSR,  cudaEventDisableTiming);
        cudaEventCreateWithFlags(&eW,    cudaEventDisableTiming);
        cudaEventCreateWithFlags(&eN,    cudaEventDisableTiming);
        cudaEventCreateWithFlags(&eG1,   cudaEventDisableTiming);
        cudaFuncSetAttribute(k_fused<1, 128, 1>,
                             cudaFuncAttributeMaxDynamicSharedMemorySize, SM_F128);
        cudaFuncSetAttribute(k_fused<2, 128, 1>,
                             cudaFuncAttributeMaxDynamicSharedMemorySize, SM_F128);
        cudaFuncSetAttribute(k_fused<2, 64, 2>,
                             cudaFuncAttributeMaxDynamicSharedMemorySize, SM_F64);
    }

    int aggBlocks  = (n + 7) / 8;
    int normBlocks = (n + 15) / 16;
    int gemmBlocks = (n + 127) / 128;

    // PDL launch helper (stream 0, 256 threads, optional dynamic smem)
    cudaLaunchAttribute pdl;
    pdl.id = cudaLaunchAttributeProgrammaticStreamSerialization;
    pdl.val.programmaticStreamSerializationAllowed = 1;
    auto pdlLaunch = [&](auto kern, int grid, int smem, auto... args) {
        cudaLaunchConfig_t c = {};
        c.gridDim = dim3(grid);
        c.blockDim = dim3(256);
        c.dynamicSmemBytes = (size_t)smem;
        c.stream = 0;
        c.attrs = &pdl;
        c.numAttrs = 1;
        cudaLaunchKernelEx(&c, kern, args...);
    };

    // fork
    cudaMemsetAsync(is64p, 1, 4);               // nonzero => int64 until refuted
    cudaEventRecord(eFork, 0);

    // s1: CSR build
    cudaStreamWaitEvent(s1, eFork, 0);
    k_zero_detect<<<1024, 256, 0, s1>>>((const int*)dst, n, e);
    k_scatter<<<1024, 256, 0, s1>>>(src, dst, e);
    cudaEventRecord(eCSR, s1);

    // s2: weight split
    cudaStreamWaitEvent(s2, eFork, 0);
    k_wsplit<<<(73728 + 255) / 256, 256, 0, s2>>>(Wself0, Wneigh0, Wneigh1,
                                                  Wneigh2, Wself3, Wneigh3);
    cudaEventRecord(eW, s2);

    // s0: norm -> qa
    k_norm<<<normBlocks, 256>>>(x, qa, n);
    cudaEventRecord(eN, 0);

    // s0: L0 self GEMM qa -> t0 (fp32), PDL vs norm
    cudaStreamWaitEvent(0, eW, 0);
    pdlLaunch(k_gemm_h<128, 0>, gemmBlocks, 0,
              (const __half*)qa, (const __half*)wh, (const __half*)wl,
              t0, qb, n);

    // s2: L0 neigh GEMM qa -> qb (fp16), parallel
    cudaStreamWaitEvent(s2, eN, 0);
    k_gemm_h<128, 1><<<gemmBlocks, 256, 0, s2>>>(qa, wh + 16384, wl + 16384,
                                                 t0, qb, n);
    cudaEventRecord(eG1, s2);

    // s0: join, then fused serial tail
    cudaStreamWaitEvent(0, eCSR, 0);
    cudaStreamWaitEvent(0, eG1, 0);

    // F1: mean-agg(t0, qb, b0) + GEMM(Wneigh1) -> qa
    pdlLaunch(k_fused<1, 128, 1>, gemmBlocks, SM_F128,
              (const float*)t0, (const __half*)qb, b0,
              (const __half*)(wh + 32768), (const __half*)(wl + 32768),
              t0, qa, n);

    // F2: gcn-agg(qa, b1) + GEMM(Wneigh2) -> qb
    pdlLaunch(k_fused<2, 128, 1>, gemmBlocks, SM_F128,
              (const float*)t0, (const __half*)qa, b1,
              (const __half*)(wh + 49152), (const __half*)(wl + 49152),
              t0, qb, n);

    // F3: gcn-agg(qb, b2) + GEMM(Wself3|Wneigh3) -> t0[n,64] + qa mirror[n,32]
    pdlLaunch(k_fused<2, 64, 2>, gemmBlocks, SM_F64,
              (const float*)t0, (const __half*)qb, b2,
              (const __half*)(wh + 65536), (const __half*)(wl + 65536),
              t0, qa, n);

    // final mean aggregation (32-dim) -> out
    pdlLaunch(k_agg_mean32, aggBlocks, 0,
              (const float*)t0, (const __half*)qa, b3, out, n);
}

// round 16
// speedup vs baseline: 1.4880x; 1.4880x over previous
#include <cuda_runtime.h>
#include <cuda_fp16.h>
#include <cstdint>

// GraphSAGE: N=50000, E=800000, 128 -> 128 -> 128 -> 32
// R14 skeleton (best stable: 184.5us): all-fp16 activations, PDL serial tail,
// fork-join CSR + wsplit, L0 GEMM pair on parallel streams, dual-output L3.
// This round: gathers use HALF-WARP per node with uint4 (16B) loads -> half
// the LDG instructions per row, 2 nodes/warp.

#define NN 50000
#define FDIM 128
#define OUTF 32
#define CAP 96

__device__ __half g_wh[73728];
__device__ __half g_wl[73728];
__device__ float  g_t0[NN * FDIM];
__device__ __half g_qa[NN * FDIM];
__device__ __half g_qb[NN * FDIM];
__device__ int    g_cnt[NN];
__device__ int    g_col[NN * CAP];
__device__ int    g_is64;

// ---------------------------------------------------------------------------
__device__ __forceinline__ void split_fp16(float v, __half& hi, __half& lo) {
    hi = __float2half_rn(v);
    lo = __float2half_rn(v - __half2float(hi));
}

__device__ __forceinline__ void cpa16(uint32_t dst, const void* src, int szz) {
    asm volatile("cp.async.ca.shared.global [%0], [%1], 16, %2;"
                 :: "r"(dst), "l"(src), "r"(szz));
}
#define CP_COMMIT asm volatile("cp.async.commit_group;" ::: "memory")
#define CP_WAIT1  asm volatile("cp.async.wait_group 1;" ::: "memory")
#define CP_WAIT0  asm volatile("cp.async.wait_group 0;" ::: "memory")

__device__ __forceinline__ void ldsm4(uint32_t r[4], uint32_t addr) {
    asm volatile("ldmatrix.sync.aligned.m8n8.x4.shared.b16 {%0,%1,%2,%3}, [%4];"
                 : "=r"(r[0]), "=r"(r[1]), "=r"(r[2]), "=r"(r[3]) : "r"(addr));
}
__device__ __forceinline__ void ldsm4t(uint32_t r[4], uint32_t addr) {
    asm volatile("ldmatrix.sync.aligned.m8n8.x4.trans.shared.b16 {%0,%1,%2,%3}, [%4];"
                 : "=r"(r[0]), "=r"(r[1]), "=r"(r[2]), "=r"(r[3]) : "r"(addr));
}
__device__ __forceinline__ void mma16816(float d[4], const uint32_t a[4],
                                         const uint32_t* b) {
    asm volatile(
        "mma.sync.aligned.m16n8k16.row.col.f32.f16.f16.f32 "
        "{%0,%1,%2,%3}, {%4,%5,%6,%7}, {%8,%9}, {%0,%1,%2,%3};"
        : "+f"(d[0]), "+f"(d[1]), "+f"(d[2]), "+f"(d[3])
        : "r"(a[0]), "r"(a[1]), "r"(a[2]), "r"(a[3]), "r"(b[0]), "r"(b[1]));
}

// ---------------------------------------------------------------------------
__device__ __forceinline__ int eidx(const void* p, int i, int is64) {
    return is64 ? (int)((const long long*)p)[i] : ((const int*)p)[i];
}

__global__ void k_zero_detect(const int* w, int n, int e) {
    for (int i = blockIdx.x * blockDim.x + threadIdx.x; i < e;
         i += gridDim.x * blockDim.x) {
        if (i < n) g_cnt[i] = 0;
        if ((i & 1) && w[i] != 0) g_is64 = 0;
    }
}

__global__ void k_scatter(const void* src, const void* dst, int e) {
    int is64 = g_is64;
    for (int i = blockIdx.x * blockDim.x + threadIdx.x; i < e;
         i += gridDim.x * blockDim.x) {
        int d = eidx(dst, i, is64);
        int p = atomicAdd(&g_cnt[d], 1);
        if (p < CAP) g_col[d * CAP + p] = eidx(src, i, is64);
    }
}

// ---------------------------------------------------------------------------
// Weight pre-split (fp16 hi/lo):
// [0)=Wself0 [16384)=Wneigh0 [32768)=Wneigh1 [49152)=Wneigh2
// [65536, 73728) = concat(Wself3 | Wneigh3) as [128 x 64]
// ---------------------------------------------------------------------------
__global__ void k_wsplit(const float* __restrict__ ws0, const float* __restrict__ wn0,
                         const float* __restrict__ wn1, const float* __restrict__ wn2,
                         const float* __restrict__ ws3, const float* __restrict__ wn3) {
    int i = blockIdx.x * blockDim.x + threadIdx.x;
    if (i >= 73728) return;
    float v;
    if (i < 16384) v = ws0[i];
    else if (i < 32768) v = wn0[i - 16384];
    else if (i < 49152) v = wn1[i - 32768];
    else if (i < 65536) v = wn2[i - 49152];
    else {
        int j = i - 65536, r = j >> 6, c = j & 63;
        v = (c < 32) ? ws3[r * 32 + c] : wn3[r * 32 + c - 32];
    }
    __half hi, lo;
    split_fp16(v, hi, lo);
    g_wh[i] = hi;
    g_wl[i] = lo;
}

// ---------------------------------------------------------------------------
// L2 normalize: half-warp per node
// ---------------------------------------------------------------------------
__global__ void k_norm(const float* __restrict__ x, __half* __restrict__ q, int n) {
    int hw = (blockIdx.x * blockDim.x + threadIdx.x) >> 4;
    int l = threadIdx.x & 15;
    if (hw >= n) return;
    size_t base = (size_t)hw * FDIM + l * 8;
    float4 a = *(const float4*)(x + base);
    float4 b = *(const float4*)(x + base + 4);
    float ss = a.x * a.x + a.y * a.y + a.z * a.z + a.w * a.w +
               b.x * b.x + b.y * b.y + b.z * b.z + b.w * b.w;
    #pragma unroll
    for (int o = 8; o; o >>= 1) ss += __shfl_xor_sync(0xFFFFFFFFu, ss, o, 16);
    float s = 1.0f / fmaxf(sqrtf(ss), 1e-12f);
    uint4 pk;
    ((__half2*)&pk)[0] = __float22half2_rn(make_float2(a.x * s, a.y * s));
    ((__half2*)&pk)[1] = __float22half2_rn(make_float2(a.z * s, a.w * s));
    ((__half2*)&pk)[2] = __float22half2_rn(make_float2(b.x * s, b.y * s));
    ((__half2*)&pk)[3] = __float22half2_rn(make_float2(b.z * s, b.w * s));
    *(uint4*)(q + base) = pk;
}

// ---------------------------------------------------------------------------
// fp16 tensor GEMM with PDL. OUTMODE: 0 = fp32 C[n,M]; 1 = fp16 Q[n,M];
// 2 = (M=64) fp32 C[n,64] + fp16 mirror of cols>=32 into Q[n,32].
// ---------------------------------------------------------------------------
template <int M>
__device__ __forceinline__ void stage_w(uint32_t dWh, uint32_t dWl,
                                        const __half* __restrict__ Wgh,
                                        const __half* __restrict__ Wgl,
                                        int k0, int tid) {
    constexpr int CW = M / 8;
    #pragma unroll
    for (int i = tid; i < 2 * 16 * CW; i += 256) {
        int half_ = i / (16 * CW), rem = i % (16 * CW);
        int r = rem / CW, seg = rem % CW;
        size_t so = (size_t)(k0 + r) * M + seg * 8;
        uint32_t dof = (uint32_t)(r * (M + 8) + seg * 8) * 2;
        if (half_ == 0) cpa16(dWh + dof, Wgh + so, 16);
        else            cpa16(dWl + dof, Wgl + so, 16);
    }
}

__device__ __forceinline__ void stage_a(uint32_t dA, const __half* __restrict__ Ag,
                                        int row0, int k0, int n, int tid) {
    int r = tid >> 1, seg = tid & 1;
    int row = row0 + r;
    int ok = (row < n) ? 16 : 0;
    size_t so = (size_t)(ok ? row : 0) * 128 + k0 + seg * 8;
    uint32_t dof = (uint32_t)(r * 24 + seg * 8) * 2;
    cpa16(dA + dof, Ag + so, ok);
}

template <int M, int OUTMODE>
__global__ void __launch_bounds__(256) k_gemm_h(
    const __half* __restrict__ Ag,
    const __half* __restrict__ Wgh, const __half* __restrict__ Wgl,
    float* __restrict__ C, __half* __restrict__ Q, int n) {
    constexpr int LDA = 24;
    constexpr int LDB = M + 8;
    constexpr int NT  = M / 16;
    __shared__ __half A[2][128 * LDA];
    __shared__ __half Wh[2][16 * LDB], Wl[2][16 * LDB];

    int tid = threadIdx.x;
    int lane = tid & 31, wid = tid >> 5;
    int row0 = blockIdx.x * 128;

    float acc[NT][2][4];
    #pragma unroll
    for (int t = 0; t < NT; t++)
        #pragma unroll
        for (int s = 0; s < 2; s++)
            #pragma unroll
            for (int c = 0; c < 4; c++) acc[t][s][c] = 0.f;

    uint32_t sA[2]  = {(uint32_t)__cvta_generic_to_shared(A[0]),
                       (uint32_t)__cvta_generic_to_shared(A[1])};
    uint32_t sWh[2] = {(uint32_t)__cvta_generic_to_shared(Wh[0]),
                       (uint32_t)__cvta_generic_to_shared(Wh[1])};
    uint32_t sWl[2] = {(uint32_t)__cvta_generic_to_shared(Wl[0]),
                       (uint32_t)__cvta_generic_to_shared(Wl[1])};

    // prologue (independent of predecessor): W chunk 0
    stage_w<M>(sWh[0], sWl[0], Wgh, Wgl, 0, tid);
    CP_COMMIT;

    cudaGridDependencySynchronize();   // predecessor produced A

    stage_a(sA[0], Ag, row0, 0, n, tid);
    CP_COMMIT;

    #pragma unroll
    for (int c = 0; c < 8; c++) {
        int b = c & 1;
        if (c < 7) {
            int nb = (c + 1) & 1;
            stage_w<M>(sWh[nb], sWl[nb], Wgh, Wgl, (c + 1) * 16, tid);
            stage_a(sA[nb], Ag, row0, (c + 1) * 16, n, tid);
            CP_COMMIT;
            CP_WAIT1;
        } else {
            CP_WAIT0;
        }
        __syncthreads();

        uint32_t aoff = ((wid * 16 + (lane & 15)) * LDA + (lane >> 4) * 8) * 2;
        uint32_t a[4];
        ldsm4(a, sA[b] + aoff);
        #pragma unroll
        for (int nt = 0; nt < NT; nt++) {
            uint32_t boff = ((lane & 15) * LDB + nt * 16 + (lane >> 4) * 8) * 2;
            uint32_t bh[4], bl[4];
            ldsm4t(bh, sWh[b] + boff);
            ldsm4t(bl, sWl[b] + boff);
            mma16816(acc[nt][0], a, bh + 0);
            mma16816(acc[nt][1], a, bh + 2);
            mma16816(acc[nt][0], a, bl + 0);
            mma16816(acc[nt][1], a, bl + 2);
        }
        __syncthreads();
    }

    int g = lane >> 2, tg = lane & 3;
    int r0 = row0 + wid * 16 + g;
    #pragma unroll
    for (int nt = 0; nt < NT; nt++) {
        #pragma unroll
        for (int s = 0; s < 2; s++) {
            int col = nt * 16 + s * 8 + tg * 2;
            float2 v01 = make_float2(acc[nt][s][0], acc[nt][s][1]);
            float2 v23 = make_float2(acc[nt][s][2], acc[nt][s][3]);
            #pragma unroll
            for (int rr = 0; rr < 2; rr++) {
                int r = r0 + rr * 8;
                float2 v = rr ? v23 : v01;
                if (r >= n) continue;
                if (OUTMODE == 0) {
                    *(float2*)(C + (size_t)r * M + col) = v;
                } else if (OUTMODE == 1) {
                    *(__half2*)(Q + (size_t)r * M + col) = __float22half2_rn(v);
                } else {  // OUTMODE 2 (M=64): fp32 + fp16 mirror of cols>=32
                    *(float2*)(C + (size_t)r * 64 + col) = v;
                    if (col >= 32)
                        *(__half2*)(Q + (size_t)r * 32 + col - 32) =
                            __float22half2_rn(v);
                }
            }
        }
    }
}

// ---------------------------------------------------------------------------
// Aggregations: HALF-WARP per node (2 nodes/warp), uint4 (16B) row loads,
// unroll-4. Bucket CSR. PDL: CSR count read pre-sync.
// ---------------------------------------------------------------------------
struct f8 { float4 a, b; };

__device__ __forceinline__ f8 h8_to_f8(uint4 raw) {
    f8 r;
    float2 f0 = __half22float2(*(__half2*)&raw.x);
    float2 f1 = __half22float2(*(__half2*)&raw.y);
    float2 f2 = __half22float2(*(__half2*)&raw.z);
    float2 f3 = __half22float2(*(__half2*)&raw.w);
    r.a = make_float4(f0.x, f0.y, f1.x, f1.y);
    r.b = make_float4(f2.x, f2.y, f3.x, f3.y);
    return r;
}
__device__ __forceinline__ void acc8(f8& a, f8 t) {
    a.a.x += t.a.x; a.a.y += t.a.y; a.a.z += t.a.z; a.a.w += t.a.w;
    a.b.x += t.b.x; a.b.y += t.b.y; a.b.z += t.b.z; a.b.w += t.b.w;
}

// gather sum over neighbors for node v; 16-lane cooperative, lane handles 8 dims
__device__ __forceinline__ f8 gather_sum16(const __half* __restrict__ q,
                                           int v, int l, int dt) {
    int L = dt < CAP ? dt : CAP;
    const int* cp = g_col + v * CAP;
    f8 acc;
    acc.a = make_float4(0.f, 0.f, 0.f, 0.f);
    acc.b = make_float4(0.f, 0.f, 0.f, 0.f);
    int j = 0;
    for (; j + 4 <= L; j += 4) {
        int4 u = *(const int4*)(cp + j);
        uint4 r0 = *(const uint4*)(q + (size_t)u.x * FDIM + l * 8);
        uint4 r1 = *(const uint4*)(q + (size_t)u.y * FDIM + l * 8);
        uint4 r2 = *(const uint4*)(q + (size_t)u.z * FDIM + l * 8);
        uint4 r3 = *(const uint4*)(q + (size_t)u.w * FDIM + l * 8);
        acc8(acc, h8_to_f8(r0)); acc8(acc, h8_to_f8(r1));
        acc8(acc, h8_to_f8(r2)); acc8(acc, h8_to_f8(r3));
    }
    for (; j < L; j++) {
        int u = cp[j];
        acc8(acc, h8_to_f8(*(const uint4*)(q + (size_t)u * FDIM + l * 8)));
    }
    return acc;
}

__device__ __forceinline__ uint4 pack_h8(float4 a, float4 b) {
    uint4 pk;
    ((__half2*)&pk)[0] = __float22half2_rn(make_float2(a.x, a.y));
    ((__half2*)&pk)[1] = __float22half2_rn(make_float2(a.z, a.w));
    ((__half2*)&pk)[2] = __float22half2_rn(make_float2(b.x, b.y));
    ((__half2*)&pk)[3] = __float22half2_rn(make_float2(b.z, b.w));
    return pk;
}

__global__ void k_agg_mean128(const float* __restrict__ tself,
                              const __half* __restrict__ qnbr,
                              const float* __restrict__ b,
                              __half* __restrict__ qout, int n) {
    int v = (blockIdx.x * blockDim.x + threadIdx.x) >> 4;
    int l = threadIdx.x & 15;
    if (v >= n) { cudaGridDependencySynchronize(); return; }
    int dt = g_cnt[v];                 // CSR ready (event-gated)
    cudaGridDependencySynchronize();
    f8 acc = gather_sum16(qnbr, v, l, dt);
    float inv = 1.0f / fmaxf((float)dt, 1.0f);
    size_t base = (size_t)v * FDIM + l * 8;
    float4 s0 = *(const float4*)(tself + base);
    float4 s1 = *(const float4*)(tself + base + 4);
    float4 b0 = *(const float4*)(b + l * 8);
    float4 b1 = *(const float4*)(b + l * 8 + 4);
    float4 oa, ob;
    oa.x = fmaxf(s0.x + acc.a.x * inv + b0.x, 0.f);
    oa.y = fmaxf(s0.y + acc.a.y * inv + b0.y, 0.f);
    oa.z = fmaxf(s0.z + acc.a.z * inv + b0.z, 0.f);
    oa.w = fmaxf(s0.w + acc.a.w * inv + b0.w, 0.f);
    ob.x = fmaxf(s1.x + acc.b.x * inv + b1.x, 0.f);
    ob.y = fmaxf(s1.y + acc.b.y * inv + b1.y, 0.f);
    ob.z = fmaxf(s1.z + acc.b.z * inv + b1.z, 0.f);
    ob.w = fmaxf(s1.w + acc.b.w * inv + b1.w, 0.f);
    *(uint4*)(qout + base) = pack_h8(oa, ob);
}

__global__ void k_agg_gcn128(const __half* __restrict__ qin,
                             const float* __restrict__ b,
                             __half* __restrict__ qout, int n) {
    int v = (blockIdx.x * blockDim.x + threadIdx.x) >> 4;
    int l = threadIdx.x & 15;
    if (v >= n) { cudaGridDependencySynchronize(); return; }
    int dt = g_cnt[v];
    cudaGridDependencySynchronize();
    f8 acc = gather_sum16(qin, v, l, dt);
    size_t base = (size_t)v * FDIM + l * 8;
    f8 sf = h8_to_f8(*(const uint4*)(qin + base));
    acc8(acc, sf);
    float inv = 1.0f / ((float)dt + 1.0f);
    float4 b0 = *(const float4*)(b + l * 8);
    float4 b1 = *(const float4*)(b + l * 8 + 4);
    float4 oa, ob;
    oa.x = fmaxf(acc.a.x * inv + b0.x, 0.f);
    oa.y = fmaxf(acc.a.y * inv + b0.y, 0.f);
    oa.z = fmaxf(acc.a.z * inv + b0.z, 0.f);
    oa.w = fmaxf(acc.a.w * inv + b0.w, 0.f);
    ob.x = fmaxf(acc.b.x * inv + b1.x, 0.f);
    ob.y = fmaxf(acc.b.y * inv + b1.y, 0.f);
    ob.z = fmaxf(acc.b.z * inv + b1.z, 0.f);
    ob.w = fmaxf(acc.b.w * inv + b1.w, 0.f);
    *(uint4*)(qout + base) = pack_h8(oa, ob);
}

// layer3: self fp32 from t[n,64] cols 0-31; neighbors fp16 from qn[n,32].
// half-warp per node: lane handles 2 dims (uint = 2 halves).
__global__ void k_agg_mean32(const float* __restrict__ t,
                             const __half* __restrict__ qn,
                             const float* __restrict__ b,
                             float* __restrict__ out, int n) {
    int v = (blockIdx.x * blockDim.x + threadIdx.x) >> 4;
    int l = threadIdx.x & 15;
    if (v >= n) { cudaGridDependencySynchronize(); return; }
    int dt = g_cnt[v];
    cudaGridDependencySynchronize();
    int L = dt < CAP ? dt : CAP;
    const int* cp = g_col + v * CAP;
    float2 acc = make_float2(0.f, 0.f);
    int j = 0;
    for (; j + 4 <= L; j += 4) {
        int4 u = *(const int4*)(cp + j);
        float2 a0 = __half22float2(*(const __half2*)(qn + (size_t)u.x * 32 + l * 2));
        float2 a1 = __half22float2(*(const __half2*)(qn + (size_t)u.y * 32 + l * 2));
        float2 a2 = __half22float2(*(const __half2*)(qn + (size_t)u.z * 32 + l * 2));
        float2 a3 = __half22float2(*(const __half2*)(qn + (size_t)u.w * 32 + l * 2));
        acc.x += a0.x + a1.x + a2.x + a3.x;
        acc.y += a0.y + a1.y + a2.y + a3.y;
    }
    for (; j < L; j++) {
        float2 a = __half22float2(*(const __half2*)(qn + (size_t)cp[j] * 32 + l * 2));
        acc.x += a.x; acc.y += a.y;
    }
    float inv = 1.0f / fmaxf((float)dt, 1.0f);
    float2 sf = *(const float2*)(t + (size_t)v * 64 + l * 2);
    float2 bb = *(const float2*)(b + l * 2);
    *(float2*)(out + (size_t)v * OUTF + l * 2) =
        make_float2(sf.x + acc.x * inv + bb.x, sf.y + acc.y * inv + bb.y);
}

// ---------------------------------------------------------------------------
extern "C" void kernel_launch(void* const* d_in, const int* in_sizes, int n_in,
                              void* d_out, int out_size) {
    const float* x       = (const float*)d_in[0];
    const void*  src     = d_in[1];
    const void*  dst     = d_in[2];
    const float* Wself0  = (const float*)d_in[3];
    const float* Wneigh0 = (const float*)d_in[4];
    const float* b0      = (const float*)d_in[5];
    const float* Wneigh1 = (const float*)d_in[6];
    const float* b1      = (const float*)d_in[7];
    const float* Wneigh2 = (const float*)d_in[8];
    const float* b2      = (const float*)d_in[9];
    const float* Wself3  = (const float*)d_in[10];
    const float* Wneigh3 = (const float*)d_in[11];
    const float* b3      = (const float*)d_in[12];
    float* out = (float*)d_out;

    int n = in_sizes[0] / FDIM;
    int e = in_sizes[1];

    __half *wh, *wl, *qa, *qb;
    float* t0;
    int* is64p;
    cudaGetSymbolAddress((void**)&wh, g_wh);
    cudaGetSymbolAddress((void**)&wl, g_wl);
    cudaGetSymbolAddress((void**)&qa, g_qa);
    cudaGetSymbolAddress((void**)&qb, g_qb);
    cudaGetSymbolAddress((void**)&t0, g_t0);
    cudaGetSymbolAddress((void**)&is64p, g_is64);

    static cudaStream_t s1 = nullptr, s2 = nullptr;
    static cudaEvent_t eFork = nullptr, eCSR = nullptr, eW = nullptr,
                       eN = nullptr, eG1 = nullptr;
    if (!s1) {
        cudaStreamCreateWithFlags(&s1, cudaStreamNonBlocking);
        cudaStreamCreateWithFlags(&s2, cudaStreamNonBlocking);
        cudaEventCreateWithFlags(&eFork, cudaEventDisableTiming);
        cudaEventCreateWithFlags(&eCSR,  cudaEventDisableTiming);
        cudaEventCreateWithFlags(&eW,    cudaEventDisableTiming);
        cudaEventCreateWithFlags(&eN,    cudaEventDisableTiming);
        cudaEventCreateWithFlags(&eG1,   cudaEventDisableTiming);
    }

    int aggBlocks  = (n + 15) / 16;   // 16 nodes per 256-thread block
    int normBlocks = (n + 15) / 16;
    int gemmBlocks = (n + 127) / 128;

    // PDL launch helper
    cudaLaunchAttribute pdl;
    pdl.id = cudaLaunchAttributeProgrammaticStreamSerialization;
    pdl.val.programmaticStreamSerializationAllowed = 1;
    auto pdlLaunch = [&](auto kern, int grid, auto... args) {
        cudaLaunchConfig_t c = {};
        c.gridDim = dim3(grid);
        c.blockDim = dim3(256);
        c.stream = 0;
        c.attrs = &pdl;
        c.numAttrs = 1;
        cudaLaunchKernelEx(&c, kern, args...);
    };

    // fork
    cudaMemsetAsync(is64p, 1, 4);               // nonzero => int64 until refuted
    cudaEventRecord(eFork, 0);

    // s1: CSR build
    cudaStreamWaitEvent(s1, eFork, 0);
    k_zero_detect<<<1024, 256, 0, s1>>>((const int*)dst, n, e);
    k_scatter<<<1024, 256, 0, s1>>>(src, dst, e);
    cudaEventRecord(eCSR, s1);

    // s2: weight split
    cudaStreamWaitEvent(s2, eFork, 0);
    k_wsplit<<<(73728 + 255) / 256, 256, 0, s2>>>(Wself0, Wneigh0, Wneigh1,
                                                  Wneigh2, Wself3, Wneigh3);
    cudaEventRecord(eW, s2);

    // s0: norm -> qa (fp16)
    k_norm<<<normBlocks, 256>>>(x, qa, n);
    cudaEventRecord(eN, 0);

    // s0: L0 self GEMM qa -> t0 (fp32), PDL vs norm
    cudaStreamWaitEvent(0, eW, 0);
    pdlLaunch(k_gemm_h<128, 0>, gemmBlocks,
              (const __half*)qa, (const __half*)wh, (const __half*)wl,
              t0, qb, n);

    // s2: L0 neigh GEMM qa -> qb (fp16), normal launch
    cudaStreamWaitEvent(s2, eN, 0);
    k_gemm_h<128, 1><<<gemmBlocks, 256, 0, s2>>>(qa, wh + 16384, wl + 16384,
                                                 t0, qb, n);
    cudaEventRecord(eG1, s2);

    // s0: join, PDL-chained serial tail (ping-pong qa/qb)
    cudaStreamWaitEvent(0, eCSR, 0);
    cudaStreamWaitEvent(0, eG1, 0);
    pdlLaunch(k_agg_mean128, aggBlocks,
              (const float*)t0, (const __half*)qb, b0, qa, n);

    pdlLaunch(k_gemm_h<128, 1>, gemmBlocks,
              (const __half*)qa, (const __half*)(wh + 32768),
              (const __half*)(wl + 32768), t0, qb, n);
    pdlLaunch(k_agg_gcn128, aggBlocks, (const __half*)qb, b1, qa, n);

    pdlLaunch(k_gemm_h<128, 1>, gemmBlocks,
              (const __half*)qa, (const __half*)(wh + 49152),
              (const __half*)(wl + 49152), t0, qb, n);
    pdlLaunch(k_agg_gcn128, aggBlocks, (const __half*)qb, b2, qa, n);

    // L3: dual-output GEMM -> t0[n,64] fp32 + qb[n,32] fp16 neighbor mirror
    pdlLaunch(k_gemm_h<64, 2>, gemmBlocks,
              (const __half*)qa, (const __half*)(wh + 65536),
              (const __half*)(wl + 65536), t0, qb, n);
    pdlLaunch(k_agg_mean32, aggBlocks,
              (const float*)t0, (const __half*)qb, b3, out, n);
}